// round 3
// baseline (speedup 1.0000x reference)
#include <cuda_runtime.h>

#define BS 16
#define H  352
#define W  1216

static constexpr int W8  = W / 8;          // 152
static constexpr int HW  = H * W;          // 428032

__device__ __forceinline__ float4 ldcs4(const float* p) {
    return __ldcs(reinterpret_cast<const float4*>(p));
}

__global__ __launch_bounds__(256)
void cspn_kernel(const float* __restrict__ Kr,   // [BS, 9, H, W]
                 const float* __restrict__ X,    // [BS, 1, H, W]
                 const float* __restrict__ X0,   // [BS, 1, H, W]
                 float* __restrict__ out)        // [BS, 1, H, W]
{
    int idx = blockIdx.x * blockDim.x + threadIdx.x;   // < BS*H*W8 exactly

    int w8 = idx % W8;
    int t  = idx / W8;
    int y  = t % H;
    int b  = t / H;
    int x  = w8 * 8;

    size_t base = (size_t)b * HW + (size_t)y * W + x;
    const float* kb = Kr + (size_t)b * 9 * HW + (size_t)y * W + x;

    float4 a0, a1;
    // Center tap (t=4) uses input0 (read-once: streaming)
    {
        float4 k0 = ldcs4(kb + (size_t)4 * HW);
        float4 k1 = ldcs4(kb + (size_t)4 * HW + 4);
        float4 v0 = __ldcs(reinterpret_cast<const float4*>(X0 + base));
        float4 v1 = __ldcs(reinterpret_cast<const float4*>(X0 + base + 4));
        a0.x = k0.x * v0.x;  a0.y = k0.y * v0.y;  a0.z = k0.z * v0.z;  a0.w = k0.w * v0.w;
        a1.x = k1.x * v1.x;  a1.y = k1.y * v1.y;  a1.z = k1.z * v1.z;  a1.w = k1.w * v1.w;
    }

    #pragma unroll
    for (int i = 0; i < 3; i++) {
        int yy = y + i - 1;
        if (yy < 0 || yy >= H) continue;   // zero-padded row: all 3 taps contribute 0

        const float* xrow = X + (size_t)b * HW + (size_t)yy * W + x;
        float4 v0   = __ldg(reinterpret_cast<const float4*>(xrow));
        float4 v1   = __ldg(reinterpret_cast<const float4*>(xrow + 4));
        float left  = (x > 0)     ? __ldg(xrow - 1) : 0.0f;
        float right = (x + 8 < W) ? __ldg(xrow + 8) : 0.0f;

        // tap (i, 0): shifted left by 1 -> values [left, v0.xyz | v0.w, v1.xyz]
        {
            float4 k0 = ldcs4(kb + (size_t)(i * 3 + 0) * HW);
            float4 k1 = ldcs4(kb + (size_t)(i * 3 + 0) * HW + 4);
            a0.x += k0.x * left;  a0.y += k0.y * v0.x;  a0.z += k0.z * v0.y;  a0.w += k0.w * v0.z;
            a1.x += k1.x * v0.w;  a1.y += k1.y * v1.x;  a1.z += k1.z * v1.y;  a1.w += k1.w * v1.z;
        }
        // tap (i, 1): aligned (skip i==1: center handled above)
        if (i != 1) {
            float4 k0 = ldcs4(kb + (size_t)(i * 3 + 1) * HW);
            float4 k1 = ldcs4(kb + (size_t)(i * 3 + 1) * HW + 4);
            a0.x += k0.x * v0.x;  a0.y += k0.y * v0.y;  a0.z += k0.z * v0.z;  a0.w += k0.w * v0.w;
            a1.x += k1.x * v1.x;  a1.y += k1.y * v1.y;  a1.z += k1.z * v1.z;  a1.w += k1.w * v1.w;
        }
        // tap (i, 2): shifted right by 1 -> values [v0.yzw, v1.x | v1.yzw, right]
        {
            float4 k0 = ldcs4(kb + (size_t)(i * 3 + 2) * HW);
            float4 k1 = ldcs4(kb + (size_t)(i * 3 + 2) * HW + 4);
            a0.x += k0.x * v0.y;  a0.y += k0.y * v0.z;  a0.z += k0.z * v0.w;  a0.w += k0.w * v1.x;
            a1.x += k1.x * v1.y;  a1.y += k1.y * v1.z;  a1.z += k1.z * v1.w;  a1.w += k1.w * right;
        }
    }

    __stcs(reinterpret_cast<float4*>(out + base), a0);
    __stcs(reinterpret_cast<float4*>(out + base + 4), a1);
}

extern "C" void kernel_launch(void* const* d_in, const int* in_sizes, int n_in,
                              void* d_out, int out_size)
{
    // metadata order: kernel [BS,9,H,W], input [BS,1,H,W], input0 [BS,1,H,W]
    const float* Kr = (const float*)d_in[0];
    const float* X  = (const float*)d_in[1];
    const float* X0 = (const float*)d_in[2];
    float* out = (float*)d_out;

    const int total = BS * H * W8;              // 856,064
    const int threads = 256;
    const int blocks = total / threads;         // 3344, exact
    cspn_kernel<<<blocks, threads>>>(Kr, X, X0, out);
}

// round 4
// speedup vs baseline: 1.0452x; 1.0452x over previous
#include <cuda_runtime.h>

#define BS 16
#define H  352
#define W  1216

static constexpr int W4  = W / 4;          // 304
static constexpr int HW  = H * W;          // 428032
static constexpr int TOTAL4 = BS * H * W4; // 1,712,128 = 6688 * 256 exactly

__global__ __launch_bounds__(256)
void cspn_kernel(const float* __restrict__ Kr,   // [BS, 9, H, W]
                 const float* __restrict__ X,    // [BS, 1, H, W]
                 const float* __restrict__ X0,   // [BS, 1, H, W]
                 float* __restrict__ out)        // [BS, 1, H, W]
{
    int idx = blockIdx.x * blockDim.x + threadIdx.x;   // < TOTAL4 exactly

    int w4 = idx % W4;
    int t  = idx / W4;
    int y  = t % H;
    int b  = t / H;
    int x  = w4 * 4;

    size_t base = (size_t)b * HW + (size_t)y * W + x;
    const float* kb = Kr + (size_t)b * 9 * HW + (size_t)y * W + x;

    float4 acc;
    // Center tap (t=4) uses input0
    {
        float4 k4 = __ldg(reinterpret_cast<const float4*>(kb + (size_t)4 * HW));
        float4 v  = __ldg(reinterpret_cast<const float4*>(X0 + base));
        acc.x = k4.x * v.x;
        acc.y = k4.y * v.y;
        acc.z = k4.z * v.z;
        acc.w = k4.w * v.w;
    }

    #pragma unroll
    for (int i = 0; i < 3; i++) {
        int yy = y + i - 1;
        if (yy < 0 || yy >= H) continue;   // zero-padded row: all 3 taps contribute 0

        const float* xrow = X + (size_t)b * HW + (size_t)yy * W + x;
        float4 v    = __ldg(reinterpret_cast<const float4*>(xrow));
        float left  = (x > 0)     ? __ldg(xrow - 1) : 0.0f;
        float right = (x + 4 < W) ? __ldg(xrow + 4) : 0.0f;

        // tap (i, 0): shift left by 1
        {
            float4 k4 = __ldg(reinterpret_cast<const float4*>(kb + (size_t)(i * 3 + 0) * HW));
            acc.x += k4.x * left;
            acc.y += k4.y * v.x;
            acc.z += k4.z * v.y;
            acc.w += k4.w * v.z;
        }
        // tap (i, 1): aligned (skip i==1: that's the center, handled above)
        if (i != 1) {
            float4 k4 = __ldg(reinterpret_cast<const float4*>(kb + (size_t)(i * 3 + 1) * HW));
            acc.x += k4.x * v.x;
            acc.y += k4.y * v.y;
            acc.z += k4.z * v.z;
            acc.w += k4.w * v.w;
        }
        // tap (i, 2): shift right by 1
        {
            float4 k4 = __ldg(reinterpret_cast<const float4*>(kb + (size_t)(i * 3 + 2) * HW));
            acc.x += k4.x * v.y;
            acc.y += k4.y * v.z;
            acc.z += k4.z * v.w;
            acc.w += k4.w * right;
        }
    }

    __stcs(reinterpret_cast<float4*>(out + base), acc);
}

extern "C" void kernel_launch(void* const* d_in, const int* in_sizes, int n_in,
                              void* d_out, int out_size)
{
    // metadata order: kernel [BS,9,H,W], input [BS,1,H,W], input0 [BS,1,H,W]
    const float* Kr = (const float*)d_in[0];
    const float* X  = (const float*)d_in[1];
    const float* X0 = (const float*)d_in[2];
    float* out = (float*)d_out;

    const int threads = 256;
    const int blocks = TOTAL4 / threads;   // 6688, exact
    cspn_kernel<<<blocks, threads>>>(Kr, X, X0, out);
}